// round 9
// baseline (speedup 1.0000x reference)
#include <cuda_runtime.h>
#include <cstdint>

// RBDispatcher — source-centric inversion.
//
// out[r]        = x[ idx_s1[ s1_to_s2[r] ] / TOP_K ]   r in [0, N_S2)
// out[N_S2 + r] = x[ idx_s1[r] / TOP_K ]               r in [0, N_S1)
//
// R3-R7 established: all schedule variants plateau at ~42us / ~5.3TB/s DRAM
// with SM<->L2 traffic ~402MB (201 read + 201 write) ~= the ~6300 B/cyc LTS
// cap. Fix = cut traffic: each x row is consumed ~3x; invert the gather so
// each row is READ ONCE and stored to all destinations from registers.
// SM<->L2 drops to ~265MB (-34%).
//
// Indices are int32 on device (JAX demotes int64 without x64).

static constexpr int D_MODEL  = 2048;
static constexpr int TOP_K    = 2;
static constexpr int VECS     = D_MODEL / 4;   // 512 float4 per row
static constexpr int NT       = 256;
static constexpr int N_TOKENS = 8192;          // source rows in x
static constexpr int MAX_FAN  = 64;            // max destinations per source

// Scratch (allocation-free per harness rules).
__device__ int g_cnt[N_TOKENS];
__device__ int g_slots[N_TOKENS * MAX_FAN];

// ---- kernel 1: zero the counters ----
__global__ void zero_kernel()
{
    int i = blockIdx.x * blockDim.x + threadIdx.x;
    if (i < N_TOKENS) g_cnt[i] = 0;
}

// ---- kernel 2: invert output-row -> source-row map ----
__global__ void invert_kernel(const int* __restrict__ idx_s1,
                              const int* __restrict__ s1_to_s2,
                              int n_s2, int n_rows)
{
    int r = blockIdx.x * blockDim.x + threadIdx.x;
    if (r >= n_rows) return;
    int e = (r < n_s2) ? idx_s1[s1_to_s2[r]] : idx_s1[r - n_s2];
    int src = e / TOP_K;
    int pos = atomicAdd(&g_cnt[src], 1);
    if (pos < MAX_FAN) g_slots[src * MAX_FAN + pos] = r;
}

// ---- kernel 3: one CTA per source row: read once, store fan-out times ----
__global__ __launch_bounds__(NT, 8)
void scatter_kernel(const float4* __restrict__ x,
                    float4* __restrict__ out)
{
    const int src = blockIdx.x;
    const int c = g_cnt[src];          // uniform, broadcast
    if (c == 0) return;

    const int t = threadIdx.x;
    const float4* __restrict__ srcp = x + (long long)src * VECS;

    // Read the 8 KiB row ONCE: 2 float4 per thread.
    float4 a0 = __ldg(&srcp[t]);
    float4 a1 = __ldg(&srcp[t + NT]);

    const int* __restrict__ slots = g_slots + src * MAX_FAN;
    for (int i = 0; i < c; i++) {
        const int r = slots[i];        // uniform, broadcast
        float4* __restrict__ dst = out + (long long)r * VECS;
        // Streaming stores: output is write-once/never-read; keep x and the
        // slot lists L2-resident.
        __stcs(&dst[t],      a0);
        __stcs(&dst[t + NT], a1);
    }
}

extern "C" void kernel_launch(void* const* d_in, const int* in_sizes, int n_in,
                              void* d_out, int out_size)
{
    const float4* x        = (const float4*)d_in[0];
    const int*    idx_s1   = (const int*)d_in[1];
    const int*    s1_to_s2 = (const int*)d_in[2];

    const int n_s1 = in_sizes[1];        // 16384
    const int n_s2 = in_sizes[2];        // 8192
    const int n_rows = n_s1 + n_s2;      // 24576

    zero_kernel<<<(N_TOKENS + NT - 1) / NT, NT>>>();
    invert_kernel<<<(n_rows + NT - 1) / NT, NT>>>(idx_s1, s1_to_s2, n_s2, n_rows);
    scatter_kernel<<<N_TOKENS, NT>>>(x, (float4*)d_out);
}